// round 14
// baseline (speedup 1.0000x reference)
#include <cuda_runtime.h>
#include <cuda_fp16.h>
#include <cstdint>
#include <math.h>

// ---------------------------------------------------------------------------
// Shapes (fixed): B=32, Lp=1024, Lq=1024, Lv=512, D=512, all fp32 row-major.
// Outputs: weightedContext [B,Lq,D], energy [B,Lq,D], precompute [B,Lp,D].
//
// R14: the GEMMs are SMEM-CROSSBAR-bound (measured 47.9% tensor duty ==
// 96% of the 49% cap for 64x32 warp tiles). New geometry: warp tile 64x64,
// CTA 128x128 with 4 warps (128 threads), 2 independent CTAs/SM — raises
// the crossbar duty cap to ~68% while keeping two barrier domains per SM
// for latency hiding. BK=64, 3-stage cp.async, fp16 score path, 2 streams.
// ---------------------------------------------------------------------------

namespace {

// ======================= Scratch (device globals) ==========================
__device__ __half g_S1h[32u * 1024u * 1024u];  // scores1 / softmax1 fp16
__device__ __half g_S2h[32u * 1024u * 512u];   // scores2 / softmax2 fp16
__device__ __half g_preH[32u * 1024u * 512u];  // fp16(pre)
__device__ __half g_qH [32u * 1024u * 512u];   // fp16(q)
__device__ __half g_vH [32u * 512u * 512u];    // fp16(v)
__device__ __half g_enH[32u * 1024u * 512u];   // fp16(energy)

// ======================= small PTX helpers =================================
__device__ __forceinline__ uint32_t smem_u32(const void* p) {
    uint32_t a;
    asm("{ .reg .u64 t; cvta.to.shared.u64 t, %1; cvt.u32.u64 %0, t; }"
        : "=r"(a) : "l"(p));
    return a;
}
__device__ __forceinline__ void cp_async16(uint32_t dst, const void* src) {
    asm volatile("cp.async.cg.shared.global [%0], [%1], 16;"
                 :: "r"(dst), "l"(src) : "memory");
}
#define CP_COMMIT() asm volatile("cp.async.commit_group;" ::: "memory")
#define CP_WAIT(n)  asm volatile("cp.async.wait_group %0;" :: "n"(n) : "memory")

__device__ __forceinline__ void mma_f16(float* c, const uint32_t* a,
                                        const uint32_t* b) {
    asm volatile(
        "mma.sync.aligned.m16n8k16.row.col.f32.f16.f16.f32 "
        "{%0,%1,%2,%3}, {%4,%5,%6,%7}, {%8,%9}, {%0,%1,%2,%3};"
        : "+f"(c[0]), "+f"(c[1]), "+f"(c[2]), "+f"(c[3])
        : "r"(a[0]), "r"(a[1]), "r"(a[2]), "r"(a[3]), "r"(b[0]), "r"(b[1]));
}
__device__ __forceinline__ void ldsm4(uint32_t* d, uint32_t addr) {
    asm volatile(
        "ldmatrix.sync.aligned.m8n8.x4.shared.b16 {%0,%1,%2,%3}, [%4];"
        : "=r"(d[0]), "=r"(d[1]), "=r"(d[2]), "=r"(d[3]) : "r"(addr));
}
__device__ __forceinline__ void ldsm4t(uint32_t* d, uint32_t addr) {
    asm volatile(
        "ldmatrix.sync.aligned.m8n8.x4.trans.shared.b16 {%0,%1,%2,%3}, [%4];"
        : "=r"(d[0]), "=r"(d[1]), "=r"(d[2]), "=r"(d[3]) : "r"(addr));
}

// ======================= fp16 mma.sync GEMM ================================
// TRANS_B=true : C = alpha * A[M,K] * B[N,K]^T  (B K-major, NT)
// TRANS_B=false: C = alpha * A[M,K] * B[K,N]    (B N-major, NN, ldsm.trans)
// CTA 128x128, 4 warps in 2(M)x2(N), warp tile 64x64, 2 CTAs/SM,
// BK=64, 3-stage cp.async, two-phase per-k16 mainloop.
constexpr int BM = 128, BN = 128, BK = 64;
constexpr int ROWA   = 144;                      // A row: 128B data + 16B pad
constexpr int ROWB_T = 144;                      // B NT row: 128B + 16B pad
constexpr int ROWB_N = 272;                      // B NN row: 256B + 16B pad
constexpr int A_BYTES = BM * ROWA;               // 18432
constexpr int STAGES = 3;
constexpr int THREADS = 128;

template <bool TRANS_B>
__global__ __launch_bounds__(THREADS, 2)
void mma_gemm_kernel(const __half* __restrict__ A, const __half* __restrict__ Bm,
                     float* __restrict__ C, __half* __restrict__ Ch,
                     int M, int N, int K, float alpha)
{
    constexpr int B_BYTES = TRANS_B ? (BN * ROWB_T) : (BK * ROWB_N);
    constexpr int STAGE_BYTES = A_BYTES + B_BYTES;

    extern __shared__ __align__(16) char dyn[];

    const int tid = threadIdx.x;
    const int wid = tid >> 5;
    const int lane = tid & 31;
    const int wm = wid & 1;                 // 2 warps along M (64 rows)
    const int wn = wid >> 1;                // 2 warps along N (64 cols)
    const int g = lane >> 2;                // frag group 0..7
    const int qq = lane & 3;                // frag quad 0..3

    const int rowA0 = blockIdx.y * BM;
    const int colB0 = blockIdx.x * BN;

    A += (size_t)blockIdx.z * M * K + (size_t)rowA0 * K;
    if (TRANS_B)
        Bm += (size_t)blockIdx.z * N * K + (size_t)colB0 * K;
    else
        Bm += (size_t)blockIdx.z * K * N + colB0;

    const uint32_t sbase = smem_u32(dyn);

    float acc[4][8][4];                     // 128 regs: 4 m16 x 8 n8 tiles
#pragma unroll
    for (int f = 0; f < 4; f++)
#pragma unroll
        for (int n = 0; n < 8; n++)
#pragma unroll
            for (int i = 0; i < 4; i++) acc[f][n][i] = 0.0f;

    const int KT = K / BK;

    auto load_tile = [&](int kt, int s) {
        const __half* gA = A + (size_t)kt * BK;
        const uint32_t dA = sbase + (uint32_t)(s * STAGE_BYTES);
        const uint32_t dB = dA + (uint32_t)A_BYTES;
#pragma unroll
        for (int i = 0; i < 8; i++) {       // A: 128 rows x 8 x 16B chunks
            const int ch = tid + i * THREADS;
            const int r = ch >> 3, c = ch & 7;
            cp_async16(dA + (uint32_t)(r * ROWA + c * 16),
                       gA + (size_t)r * K + c * 8);
        }
        if (TRANS_B) {
            const __half* gB = Bm + (size_t)kt * BK;
#pragma unroll
            for (int i = 0; i < 8; i++) {   // B: 128 rows x 8 chunks
                const int ch = tid + i * THREADS;
                const int r = ch >> 3, c = ch & 7;
                cp_async16(dB + (uint32_t)(r * ROWB_T + c * 16),
                           gB + (size_t)r * K + c * 8);
            }
        } else {
            const __half* gB = Bm + (size_t)(kt * BK) * N;
#pragma unroll
            for (int i = 0; i < 8; i++) {   // B: 64 rows x 16 chunks
                const int ch = tid + i * THREADS;
                const int r = ch >> 4, c = ch & 15;
                cp_async16(dB + (uint32_t)(r * ROWB_N + c * 16),
                           gB + (size_t)r * N + c * 8);
            }
        }
    };

    // prologue: stages 0..1 in flight
#pragma unroll
    for (int p = 0; p < STAGES - 1; p++) {
        load_tile(p, p);
        CP_COMMIT();
    }

    // fragment address components
    const int aRow = (lane & 15);
    const int aKof = (lane >> 4) * 16;
    const int bRowT = (lane & 7) + ((lane >> 4) << 3);
    const int bKofT = ((lane >> 3) & 1) * 16;
    const int q8 = lane >> 3;
    const int bKrowN = ((q8 & 1) << 3) + (lane & 7);
    const int bNofN = (q8 >> 1) << 4;

    for (int kt = 0; kt < KT; kt++) {
        const int s = kt % STAGES;
        const int ktn = kt + STAGES - 1;
        if (ktn < KT) load_tile(ktn, ktn % STAGES);
        CP_COMMIT();                         // unconditional: drains tail
        CP_WAIT(STAGES - 2);                 // tile kt resident
        __syncthreads();

        const uint32_t uA = sbase + (uint32_t)(s * STAGE_BYTES);
        const uint32_t uB = uA + (uint32_t)A_BYTES;

#pragma unroll
        for (int ks = 0; ks < 4; ks++) {     // four k16 steps per BK=64
            uint32_t a[4][4], bl[4][4];
#pragma unroll
            for (int f = 0; f < 4; f++) {
                const int row = wm * 64 + f * 16 + aRow;
                ldsm4(a[f], uA + (uint32_t)(row * ROWA + ks * 32 + aKof));
            }
            if (TRANS_B) {
#pragma unroll
                for (int p = 0; p < 4; p++) {
                    const int row = wn * 64 + p * 16 + bRowT;
                    ldsm4(bl[p], uB + (uint32_t)(row * ROWB_T + ks * 32 + bKofT));
                }
            } else {
#pragma unroll
                for (int p = 0; p < 4; p++) {
                    const int krow = ks * 16 + bKrowN;
                    const int nby = (wn * 64 + p * 16) * 2 + bNofN;
                    ldsm4t(bl[p], uB + (uint32_t)(krow * ROWB_N + nby));
                }
            }
#pragma unroll
            for (int f = 0; f < 4; f++)
#pragma unroll
                for (int n = 0; n < 8; n++)
                    mma_f16(acc[f][n], a[f], &bl[n >> 1][(n & 1) * 2]);
        }
        __syncthreads();                     // tile kt reads done (slot reuse)
    }

    // epilogue: optional fp32 store, optional fp16 store
    float* Cb = C ? C + (size_t)blockIdx.z * M * N : (float*)0;
    __half* Chb = Ch ? Ch + (size_t)blockIdx.z * M * N : (__half*)0;
#pragma unroll
    for (int f = 0; f < 4; f++) {
        const int row = rowA0 + wm * 64 + f * 16 + g;
#pragma unroll
        for (int n = 0; n < 8; n++) {
            const int col = colB0 + wn * 64 + n * 8 + 2 * qq;
            float2 v0, v1;
            v0.x = acc[f][n][0] * alpha;
            v0.y = acc[f][n][1] * alpha;
            v1.x = acc[f][n][2] * alpha;
            v1.y = acc[f][n][3] * alpha;
            if (Cb) {
                *reinterpret_cast<float2*>(Cb + (size_t)row * N + col) = v0;
                *reinterpret_cast<float2*>(Cb + (size_t)(row + 8) * N + col) = v1;
            }
            if (Chb) {
                *reinterpret_cast<__half2*>(Chb + (size_t)row * N + col) =
                    __float22half2_rn(v0);
                *reinterpret_cast<__half2*>(Chb + (size_t)(row + 8) * N + col) =
                    __float22half2_rn(v1);
            }
        }
    }
}

constexpr int SMEM_NT = STAGES * (A_BYTES + BN * ROWB_T);  // 110592
constexpr int SMEM_NN = STAGES * (A_BYTES + BK * ROWB_N);  // 107520

// ======================= fp32 -> fp16 convert ==============================
__global__ __launch_bounds__(256)
void h_convert_kernel(const float* __restrict__ in, __half* __restrict__ out)
{
    const size_t i = ((size_t)blockIdx.x * 256 + threadIdx.x) * 8;
    float4 v0 = *reinterpret_cast<const float4*>(in + i);
    float4 v1 = *reinterpret_cast<const float4*>(in + i + 4);
    __half2 h[4];
    h[0] = __float22half2_rn(make_float2(v0.x, v0.y));
    h[1] = __float22half2_rn(make_float2(v0.z, v0.w));
    h[2] = __float22half2_rn(make_float2(v1.x, v1.y));
    h[3] = __float22half2_rn(make_float2(v1.z, v1.w));
    *reinterpret_cast<uint4*>(out + i) = *reinterpret_cast<uint4*>(h);
}

// ======================= row softmax (fp16 in place, fp32 math) ============
template <int ELEMS>   // halves per thread; W = 256*ELEMS
__global__ __launch_bounds__(256)
void softmax_rows_h_kernel(__half* __restrict__ Sh, int W)
{
    __half* ph = Sh + (size_t)blockIdx.x * W + (size_t)threadIdx.x * ELEMS;
    const int tid = threadIdx.x;

    float vals[ELEMS];
    if (ELEMS == 4) {
        uint2 raw = *reinterpret_cast<const uint2*>(ph);
        __half2 h0 = *reinterpret_cast<__half2*>(&raw.x);
        __half2 h1 = *reinterpret_cast<__half2*>(&raw.y);
        float2 f0 = __half22float2(h0);
        float2 f1 = __half22float2(h1);
        vals[0] = f0.x; vals[1] = f0.y; vals[2] = f1.x; vals[3] = f1.y;
    } else {
        uint32_t raw = *reinterpret_cast<const uint32_t*>(ph);
        __half2 h0 = *reinterpret_cast<__half2*>(&raw);
        float2 f0 = __half22float2(h0);
        vals[0] = f0.x; vals[1] = f0.y;
    }

    float m = vals[0];
#pragma unroll
    for (int i = 1; i < ELEMS; i++) m = fmaxf(m, vals[i]);

    __shared__ float red[8];
    __shared__ float bc;

#pragma unroll
    for (int o = 16; o > 0; o >>= 1)
        m = fmaxf(m, __shfl_xor_sync(0xffffffffu, m, o));
    if ((tid & 31) == 0) red[tid >> 5] = m;
    __syncthreads();
    if (tid == 0) {
        float t = red[0];
#pragma unroll
        for (int i = 1; i < 8; i++) t = fmaxf(t, red[i]);
        bc = t;
    }
    __syncthreads();
    m = bc;

    float s = 0.0f;
#pragma unroll
    for (int i = 0; i < ELEMS; i++) {
        vals[i] = expf(vals[i] - m);
        s += vals[i];
    }
    __syncthreads();

#pragma unroll
    for (int o = 16; o > 0; o >>= 1)
        s += __shfl_xor_sync(0xffffffffu, s, o);
    if ((tid & 31) == 0) red[tid >> 5] = s;
    __syncthreads();
    if (tid == 0) {
        float t = red[0];
#pragma unroll
        for (int i = 1; i < 8; i++) t += red[i];
        bc = 1.0f / t;
    }
    __syncthreads();
    const float inv = bc;

    if (ELEMS == 4) {
        __half2 h0 = __float22half2_rn(make_float2(vals[0] * inv, vals[1] * inv));
        __half2 h1 = __float22half2_rn(make_float2(vals[2] * inv, vals[3] * inv));
        uint2 o;
        o.x = *reinterpret_cast<uint32_t*>(&h0);
        o.y = *reinterpret_cast<uint32_t*>(&h1);
        *reinterpret_cast<uint2*>(ph) = o;
    } else {
        __half2 h0 = __float22half2_rn(make_float2(vals[0] * inv, vals[1] * inv));
        *reinterpret_cast<uint32_t*>(ph) = *reinterpret_cast<uint32_t*>(&h0);
    }
}

}  // namespace

// ===========================================================================
extern "C" void kernel_launch(void* const* d_in, const int* in_sizes, int n_in,
                              void* d_out, int out_size)
{
    const float* pre = (const float*)d_in[0];  // [32,1024,512]
    const float* q   = (const float*)d_in[1];  // [32,1024,512]
    const float* v   = (const float*)d_in[2];  // [32, 512,512]
    float* out = (float*)d_out;

    const int B = 32, Lp = 1024, Lq = 1024, Lv = 512, D = 512;
    const float scale = 0.04419417382415922f;  // 1/sqrt(512)

    float* wc     = out;                           // [B,Lq,D]
    float* energy = out + (size_t)B * Lq * D;      // [B,Lq,D]
    float* prec   = out + 2 * (size_t)B * Lq * D;  // [B,Lp,D]

    __half *S1h, *S2h, *preH, *qH, *vH, *enH;
    cudaGetSymbolAddress((void**)&S1h, g_S1h);
    cudaGetSymbolAddress((void**)&S2h, g_S2h);
    cudaGetSymbolAddress((void**)&preH, g_preH);
    cudaGetSymbolAddress((void**)&qH, g_qH);
    cudaGetSymbolAddress((void**)&vH, g_vH);
    cudaGetSymbolAddress((void**)&enH, g_enH);

    // one-time setup (first call is the uncaptured correctness run)
    static cudaStream_t sB = 0;
    static cudaEvent_t eFork = 0, eJoin = 0;
    if (!sB) {
        cudaStreamCreateWithFlags(&sB, cudaStreamNonBlocking);
        cudaEventCreateWithFlags(&eFork, cudaEventDisableTiming);
        cudaEventCreateWithFlags(&eJoin, cudaEventDisableTiming);
        cudaFuncSetAttribute(mma_gemm_kernel<true>,
                             cudaFuncAttributeMaxDynamicSharedMemorySize,
                             SMEM_NT);
        cudaFuncSetAttribute(mma_gemm_kernel<false>,
                             cudaFuncAttributeMaxDynamicSharedMemorySize,
                             SMEM_NN);
    }

    const int nPQ = B * Lp * D;   // 16.8M
    const int nV  = B * Lv * D;   // 8.4M
    const dim3 blk(THREADS);
    cudaStream_t sA = 0;          // legacy default stream (captured origin)

    // shared prolog on stream A: qH needed by both chains
    h_convert_kernel<<<nPQ / (256 * 8), 256, 0, sA>>>(q, qH);

    // fork chain B (pre convert on A overlaps v convert on B)
    cudaEventRecord(eFork, sA);
    cudaStreamWaitEvent(sB, eFork, 0);

    h_convert_kernel<<<nPQ / (256 * 8), 256, 0, sA>>>(pre, preH);

    // ---- chain B (stream sB): energy + weightedContext ----
    h_convert_kernel<<<nV / (256 * 8), 256, 0, sB>>>(v, vH);
    mma_gemm_kernel<true><<<dim3(Lv / BN, Lq / BM, B), blk, SMEM_NT, sB>>>(
        qH, vH, nullptr, S2h, Lq, Lv, D, scale);
    softmax_rows_h_kernel<2><<<B * Lq, 256, 0, sB>>>(S2h, Lv);
    mma_gemm_kernel<false><<<dim3(D / BN, Lq / BM, B), blk, SMEM_NN, sB>>>(
        S2h, vH, energy, enH, Lq, D, Lv, 1.0f);
    mma_gemm_kernel<false><<<dim3(D / BN, Lq / BM, B), blk, SMEM_NN, sB>>>(
        enH, vH, wc, nullptr, Lq, D, Lv, 1.0f);

    // ---- chain A (stream sA): precompute ----
    mma_gemm_kernel<true><<<dim3(Lq / BN, Lp / BM, B), blk, SMEM_NT, sA>>>(
        preH, qH, nullptr, S1h, Lp, Lq, D, scale);
    softmax_rows_h_kernel<4><<<B * Lp, 256, 0, sA>>>(S1h, Lq);
    mma_gemm_kernel<false><<<dim3(D / BN, Lp / BM, B), blk, SMEM_NN, sA>>>(
        S1h, qH, prec, nullptr, Lp, D, Lq, 1.0f);

    // join
    cudaEventRecord(eJoin, sB);
    cudaStreamWaitEvent(sA, eJoin, 0);
}

// round 15
// speedup vs baseline: 1.0455x; 1.0455x over previous
#include <cuda_runtime.h>
#include <cuda_fp16.h>
#include <cstdint>
#include <math.h>

// ---------------------------------------------------------------------------
// Shapes (fixed): B=32, Lp=1024, Lq=1024, Lv=512, D=512, all fp32 row-major.
// Outputs: weightedContext [B,Lq,D], energy [B,Lq,D], precompute [B,Lp,D].
//
// R15 = R13 (best: 128x128 CTA, 8 warps of 64x32, BK=64, 3-stage cp.async,
// fp16 score path, two streams) with ONE barrier per K-tile: the loop is
// reordered to wait+sync BEFORE issuing the prefetch into the recycled slot,
// which makes the trailing barrier unnecessary. Measured R13 sits at the
// smem-crossbar duty cap (~48%); this only trims fixed barrier overhead.
// ---------------------------------------------------------------------------

namespace {

// ======================= Scratch (device globals) ==========================
__device__ __half g_S1h[32u * 1024u * 1024u];  // scores1 / softmax1 fp16
__device__ __half g_S2h[32u * 1024u * 512u];   // scores2 / softmax2 fp16
__device__ __half g_preH[32u * 1024u * 512u];  // fp16(pre)
__device__ __half g_qH [32u * 1024u * 512u];   // fp16(q)
__device__ __half g_vH [32u * 512u * 512u];    // fp16(v)
__device__ __half g_enH[32u * 1024u * 512u];   // fp16(energy)

// ======================= small PTX helpers =================================
__device__ __forceinline__ uint32_t smem_u32(const void* p) {
    uint32_t a;
    asm("{ .reg .u64 t; cvta.to.shared.u64 t, %1; cvt.u32.u64 %0, t; }"
        : "=r"(a) : "l"(p));
    return a;
}
__device__ __forceinline__ void cp_async16(uint32_t dst, const void* src) {
    asm volatile("cp.async.cg.shared.global [%0], [%1], 16;"
                 :: "r"(dst), "l"(src) : "memory");
}
#define CP_COMMIT() asm volatile("cp.async.commit_group;" ::: "memory")
#define CP_WAIT(n)  asm volatile("cp.async.wait_group %0;" :: "n"(n) : "memory")

__device__ __forceinline__ void mma_f16(float* c, const uint32_t* a,
                                        const uint32_t* b) {
    asm volatile(
        "mma.sync.aligned.m16n8k16.row.col.f32.f16.f16.f32 "
        "{%0,%1,%2,%3}, {%4,%5,%6,%7}, {%8,%9}, {%0,%1,%2,%3};"
        : "+f"(c[0]), "+f"(c[1]), "+f"(c[2]), "+f"(c[3])
        : "r"(a[0]), "r"(a[1]), "r"(a[2]), "r"(a[3]), "r"(b[0]), "r"(b[1]));
}
__device__ __forceinline__ void ldsm4(uint32_t* d, uint32_t addr) {
    asm volatile(
        "ldmatrix.sync.aligned.m8n8.x4.shared.b16 {%0,%1,%2,%3}, [%4];"
        : "=r"(d[0]), "=r"(d[1]), "=r"(d[2]), "=r"(d[3]) : "r"(addr));
}
__device__ __forceinline__ void ldsm4t(uint32_t* d, uint32_t addr) {
    asm volatile(
        "ldmatrix.sync.aligned.m8n8.x4.trans.shared.b16 {%0,%1,%2,%3}, [%4];"
        : "=r"(d[0]), "=r"(d[1]), "=r"(d[2]), "=r"(d[3]) : "r"(addr));
}

// ======================= fp16 mma.sync GEMM ================================
// TRANS_B=true : C = alpha * A[M,K] * B[N,K]^T  (B K-major, NT)
// TRANS_B=false: C = alpha * A[M,K] * B[K,N]    (B N-major, NN, ldsm.trans)
// CTA 128x128, BK=64, 8 warps (warp tile 64x32), 3-stage cp.async pipeline,
// ONE __syncthreads per K-tile, two-phase per-k16 fragment loads.
constexpr int BM = 128, BN = 128, BK = 64;
constexpr int ROWA   = 144;                      // A row: 128B data + 16B pad
constexpr int ROWB_T = 144;                      // B NT row: 128B + 16B pad
constexpr int ROWB_N = 272;                      // B NN row: 256B + 16B pad
constexpr int A_BYTES = BM * ROWA;               // 18432
constexpr int STAGES = 3;

template <bool TRANS_B>
__global__ __launch_bounds__(256, 2)
void mma_gemm_kernel(const __half* __restrict__ A, const __half* __restrict__ Bm,
                     float* __restrict__ C, __half* __restrict__ Ch,
                     int M, int N, int K, float alpha)
{
    constexpr int B_BYTES = TRANS_B ? (BN * ROWB_T) : (BK * ROWB_N);
    constexpr int STAGE_BYTES = A_BYTES + B_BYTES;

    extern __shared__ __align__(16) char dyn[];

    const int tid = threadIdx.x;
    const int wid = tid >> 5;
    const int lane = tid & 31;
    const int wm = wid & 1;                 // 2 warps along M
    const int wn = wid >> 1;                // 4 warps along N
    const int g = lane >> 2;                // frag group 0..7
    const int qq = lane & 3;                // frag quad 0..3

    const int rowA0 = blockIdx.y * BM;
    const int colB0 = blockIdx.x * BN;

    A += (size_t)blockIdx.z * M * K + (size_t)rowA0 * K;
    if (TRANS_B)
        Bm += (size_t)blockIdx.z * N * K + (size_t)colB0 * K;
    else
        Bm += (size_t)blockIdx.z * K * N + colB0;

    const uint32_t sbase = smem_u32(dyn);

    float acc[4][4][4];
#pragma unroll
    for (int f = 0; f < 4; f++)
#pragma unroll
        for (int n = 0; n < 4; n++)
#pragma unroll
            for (int i = 0; i < 4; i++) acc[f][n][i] = 0.0f;

    const int KT = K / BK;

    auto load_tile = [&](int kt, int s) {
        const __half* gA = A + (size_t)kt * BK;
        const uint32_t dA = sbase + (uint32_t)(s * STAGE_BYTES);
        const uint32_t dB = dA + (uint32_t)A_BYTES;
#pragma unroll
        for (int i = 0; i < 4; i++) {       // A: 128 rows x 8 x 16B chunks
            const int ch = tid + i * 256;
            const int r = ch >> 3, c = ch & 7;
            cp_async16(dA + (uint32_t)(r * ROWA + c * 16),
                       gA + (size_t)r * K + c * 8);
        }
        if (TRANS_B) {
            const __half* gB = Bm + (size_t)kt * BK;
#pragma unroll
            for (int i = 0; i < 4; i++) {   // B: 128 rows x 8 chunks
                const int ch = tid + i * 256;
                const int r = ch >> 3, c = ch & 7;
                cp_async16(dB + (uint32_t)(r * ROWB_T + c * 16),
                           gB + (size_t)r * K + c * 8);
            }
        } else {
            const __half* gB = Bm + (size_t)(kt * BK) * N;
#pragma unroll
            for (int i = 0; i < 4; i++) {   // B: 64 rows x 16 chunks
                const int ch = tid + i * 256;
                const int r = ch >> 4, c = ch & 15;
                cp_async16(dB + (uint32_t)(r * ROWB_N + c * 16),
                           gB + (size_t)r * N + c * 8);
            }
        }
    };

    // prologue: stages 0..1 in flight
#pragma unroll
    for (int p = 0; p < STAGES - 1; p++) {
        load_tile(p, p);
        CP_COMMIT();
    }

    // fragment address components
    const int aRow = (lane & 15);
    const int aKof = (lane >> 4) * 16;
    const int bRowT = (lane & 7) + ((lane >> 4) << 3);
    const int bKofT = ((lane >> 3) & 1) * 16;
    const int q8 = lane >> 3;
    const int bKrowN = ((q8 & 1) << 3) + (lane & 7);
    const int bNofN = (q8 >> 1) << 4;

    for (int kt = 0; kt < KT; kt++) {
        // tile kt resident; barrier also closes all reads of tile kt-1
        CP_WAIT(STAGES - 2);
        __syncthreads();

        // prefetch tile kt+2 into slot (kt+2)%3 == (kt-1)%3 — safe: every
        // warp's reads of tile kt-1 completed before the barrier above.
        const int ktn = kt + STAGES - 1;
        if (ktn < KT) load_tile(ktn, ktn % STAGES);
        CP_COMMIT();                         // unconditional: drains tail

        const uint32_t uA = sbase + (uint32_t)((kt % STAGES) * STAGE_BYTES);
        const uint32_t uB = uA + (uint32_t)A_BYTES;

#pragma unroll
        for (int ks = 0; ks < 4; ks++) {     // four k16 steps per BK=64
            uint32_t a[4][4], bl[2][4];
#pragma unroll
            for (int f = 0; f < 4; f++) {
                const int row = wm * 64 + f * 16 + aRow;
                ldsm4(a[f], uA + (uint32_t)(row * ROWA + ks * 32 + aKof));
            }
            if (TRANS_B) {
#pragma unroll
                for (int p = 0; p < 2; p++) {
                    const int row = wn * 32 + p * 16 + bRowT;
                    ldsm4(bl[p], uB + (uint32_t)(row * ROWB_T + ks * 32 + bKofT));
                }
            } else {
#pragma unroll
                for (int p = 0; p < 2; p++) {
                    const int krow = ks * 16 + bKrowN;
                    const int nby = (wn * 32 + p * 16) * 2 + bNofN;
                    ldsm4t(bl[p], uB + (uint32_t)(krow * ROWB_N + nby));
                }
            }
#pragma unroll
            for (int f = 0; f < 4; f++)
#pragma unroll
                for (int n = 0; n < 4; n++)
                    mma_f16(acc[f][n], a[f], &bl[n >> 1][(n & 1) * 2]);
        }
    }

    // epilogue: optional fp32 store, optional fp16 store
    float* Cb = C ? C + (size_t)blockIdx.z * M * N : (float*)0;
    __half* Chb = Ch ? Ch + (size_t)blockIdx.z * M * N : (__half*)0;
#pragma unroll
    for (int f = 0; f < 4; f++) {
        const int row = rowA0 + wm * 64 + f * 16 + g;
#pragma unroll
        for (int n = 0; n < 4; n++) {
            const int col = colB0 + wn * 32 + n * 8 + 2 * qq;
            float2 v0, v1;
            v0.x = acc[f][n][0] * alpha;
            v0.y = acc[f][n][1] * alpha;
            v1.x = acc[f][n][2] * alpha;
            v1.y = acc[f][n][3] * alpha;
            if (Cb) {
                *reinterpret_cast<float2*>(Cb + (size_t)row * N + col) = v0;
                *reinterpret_cast<float2*>(Cb + (size_t)(row + 8) * N + col) = v1;
            }
            if (Chb) {
                *reinterpret_cast<__half2*>(Chb + (size_t)row * N + col) =
                    __float22half2_rn(v0);
                *reinterpret_cast<__half2*>(Chb + (size_t)(row + 8) * N + col) =
                    __float22half2_rn(v1);
            }
        }
    }
}

constexpr int SMEM_NT = STAGES * (A_BYTES + BN * ROWB_T);  // 110592
constexpr int SMEM_NN = STAGES * (A_BYTES + BK * ROWB_N);  // 107520

// ======================= fp32 -> fp16 convert ==============================
__global__ __launch_bounds__(256)
void h_convert_kernel(const float* __restrict__ in, __half* __restrict__ out)
{
    const size_t i = ((size_t)blockIdx.x * 256 + threadIdx.x) * 8;
    float4 v0 = *reinterpret_cast<const float4*>(in + i);
    float4 v1 = *reinterpret_cast<const float4*>(in + i + 4);
    __half2 h[4];
    h[0] = __float22half2_rn(make_float2(v0.x, v0.y));
    h[1] = __float22half2_rn(make_float2(v0.z, v0.w));
    h[2] = __float22half2_rn(make_float2(v1.x, v1.y));
    h[3] = __float22half2_rn(make_float2(v1.z, v1.w));
    *reinterpret_cast<uint4*>(out + i) = *reinterpret_cast<uint4*>(h);
}

// ======================= row softmax (fp16 in place, fp32 math) ============
template <int ELEMS>   // halves per thread; W = 256*ELEMS
__global__ __launch_bounds__(256)
void softmax_rows_h_kernel(__half* __restrict__ Sh, int W)
{
    __half* ph = Sh + (size_t)blockIdx.x * W + (size_t)threadIdx.x * ELEMS;
    const int tid = threadIdx.x;

    float vals[ELEMS];
    if (ELEMS == 4) {
        uint2 raw = *reinterpret_cast<const uint2*>(ph);
        __half2 h0 = *reinterpret_cast<__half2*>(&raw.x);
        __half2 h1 = *reinterpret_cast<__half2*>(&raw.y);
        float2 f0 = __half22float2(h0);
        float2 f1 = __half22float2(h1);
        vals[0] = f0.x; vals[1] = f0.y; vals[2] = f1.x; vals[3] = f1.y;
    } else {
        uint32_t raw = *reinterpret_cast<const uint32_t*>(ph);
        __half2 h0 = *reinterpret_cast<__half2*>(&raw);
        float2 f0 = __half22float2(h0);
        vals[0] = f0.x; vals[1] = f0.y;
    }

    float m = vals[0];
#pragma unroll
    for (int i = 1; i < ELEMS; i++) m = fmaxf(m, vals[i]);

    __shared__ float red[8];
    __shared__ float bc;

#pragma unroll
    for (int o = 16; o > 0; o >>= 1)
        m = fmaxf(m, __shfl_xor_sync(0xffffffffu, m, o));
    if ((tid & 31) == 0) red[tid >> 5] = m;
    __syncthreads();
    if (tid == 0) {
        float t = red[0];
#pragma unroll
        for (int i = 1; i < 8; i++) t = fmaxf(t, red[i]);
        bc = t;
    }
    __syncthreads();
    m = bc;

    float s = 0.0f;
#pragma unroll
    for (int i = 0; i < ELEMS; i++) {
        vals[i] = expf(vals[i] - m);
        s += vals[i];
    }
    __syncthreads();

#pragma unroll
    for (int o = 16; o > 0; o >>= 1)
        s += __shfl_xor_sync(0xffffffffu, s, o);
    if ((tid & 31) == 0) red[tid >> 5] = s;
    __syncthreads();
    if (tid == 0) {
        float t = red[0];
#pragma unroll
        for (int i = 1; i < 8; i++) t += red[i];
        bc = 1.0f / t;
    }
    __syncthreads();
    const float inv = bc;

    if (ELEMS == 4) {
        __half2 h0 = __float22half2_rn(make_float2(vals[0] * inv, vals[1] * inv));
        __half2 h1 = __float22half2_rn(make_float2(vals[2] * inv, vals[3] * inv));
        uint2 o;
        o.x = *reinterpret_cast<uint32_t*>(&h0);
        o.y = *reinterpret_cast<uint32_t*>(&h1);
        *reinterpret_cast<uint2*>(ph) = o;
    } else {
        __half2 h0 = __float22half2_rn(make_float2(vals[0] * inv, vals[1] * inv));
        *reinterpret_cast<uint32_t*>(ph) = *reinterpret_cast<uint32_t*>(&h0);
    }
}

}  // namespace

// ===========================================================================
extern "C" void kernel_launch(void* const* d_in, const int* in_sizes, int n_in,
                              void* d_out, int out_size)
{
    const float* pre = (const float*)d_in[0];  // [32,1024,512]
    const float* q   = (const float*)d_in[1];  // [32,1024,512]
    const float* v   = (const float*)d_in[2];  // [32, 512,512]
    float* out = (float*)d_out;

    const int B = 32, Lp = 1024, Lq = 1024, Lv = 512, D = 512;
    const float scale = 0.04419417382415922f;  // 1/sqrt(512)

    float* wc     = out;                           // [B,Lq,D]
    float* energy = out + (size_t)B * Lq * D;      // [B,Lq,D]
    float* prec   = out + 2 * (size_t)B * Lq * D;  // [B,Lp,D]

    __half *S1h, *S2h, *preH, *qH, *vH, *enH;
    cudaGetSymbolAddress((void**)&S1h, g_S1h);
    cudaGetSymbolAddress((void**)&S2h, g_S2h);
    cudaGetSymbolAddress((void**)&preH, g_preH);
    cudaGetSymbolAddress((void**)&qH, g_qH);
    cudaGetSymbolAddress((void**)&vH, g_vH);
    cudaGetSymbolAddress((void**)&enH, g_enH);

    // one-time setup (first call is the uncaptured correctness run)
    static cudaStream_t sB = 0;
    static cudaEvent_t eFork = 0, eJoin = 0;
    if (!sB) {
        cudaStreamCreateWithFlags(&sB, cudaStreamNonBlocking);
        cudaEventCreateWithFlags(&eFork, cudaEventDisableTiming);
        cudaEventCreateWithFlags(&eJoin, cudaEventDisableTiming);
        cudaFuncSetAttribute(mma_gemm_kernel<true>,
                             cudaFuncAttributeMaxDynamicSharedMemorySize,
                             SMEM_NT);
        cudaFuncSetAttribute(mma_gemm_kernel<false>,
                             cudaFuncAttributeMaxDynamicSharedMemorySize,
                             SMEM_NN);
    }

    const int nPQ = B * Lp * D;   // 16.8M
    const int nV  = B * Lv * D;   // 8.4M
    const dim3 blk(256);
    cudaStream_t sA = 0;          // legacy default stream (captured origin)

    // shared prolog on stream A: qH needed by both chains
    h_convert_kernel<<<nPQ / (256 * 8), 256, 0, sA>>>(q, qH);

    // fork chain B (pre convert on A overlaps v convert on B)
    cudaEventRecord(eFork, sA);
    cudaStreamWaitEvent(sB, eFork, 0);

    h_convert_kernel<<<nPQ / (256 * 8), 256, 0, sA>>>(pre, preH);

    // ---- chain B (stream sB): energy + weightedContext ----
    h_convert_kernel<<<nV / (256 * 8), 256, 0, sB>>>(v, vH);
    mma_gemm_kernel<true><<<dim3(Lv / BN, Lq / BM, B), blk, SMEM_NT, sB>>>(
        qH, vH, nullptr, S2h, Lq, Lv, D, scale);
    softmax_rows_h_kernel<2><<<B * Lq, 256, 0, sB>>>(S2h, Lv);
    mma_gemm_kernel<false><<<dim3(D / BN, Lq / BM, B), blk, SMEM_NN, sB>>>(
        S2h, vH, energy, enH, Lq, D, Lv, 1.0f);
    mma_gemm_kernel<false><<<dim3(D / BN, Lq / BM, B), blk, SMEM_NN, sB>>>(
        enH, vH, wc, nullptr, Lq, D, Lv, 1.0f);

    // ---- chain A (stream sA): precompute ----
    mma_gemm_kernel<true><<<dim3(Lq / BN, Lp / BM, B), blk, SMEM_NT, sA>>>(
        preH, qH, nullptr, S1h, Lp, Lq, D, scale);
    softmax_rows_h_kernel<4><<<B * Lp, 256, 0, sA>>>(S1h, Lq);
    mma_gemm_kernel<false><<<dim3(D / BN, Lp / BM, B), blk, SMEM_NN, sA>>>(
        S1h, qH, prec, nullptr, Lp, D, Lq, 1.0f);

    // join
    cudaEventRecord(eJoin, sB);
    cudaStreamWaitEvent(sA, eJoin, 0);
}

// round 16
// speedup vs baseline: 1.0529x; 1.0071x over previous
#include <cuda_runtime.h>
#include <cuda_fp16.h>
#include <cstdint>
#include <math.h>

// ---------------------------------------------------------------------------
// Shapes (fixed): B=32, Lp=1024, Lq=1024, Lv=512, D=512, all fp32 row-major.
// Outputs: weightedContext [B,Lq,D], energy [B,Lq,D], precompute [B,Lp,D].
//
// R16 = R15 GEMM core (at its measured smem-crossbar roofline: 49.6% tensor
// duty == the 50% cap) with seam reduction: S1+S2 score GEMMs merged into
// ONE launch (better wave packing), the three fp32->fp16 converts merged
// into one kernel, balanced stream fork after the merged GEMM.
// ---------------------------------------------------------------------------

namespace {

// ======================= Scratch (device globals) ==========================
__device__ __half g_S1h[32u * 1024u * 1024u];  // scores1 / softmax1 fp16
__device__ __half g_S2h[32u * 1024u * 512u];   // scores2 / softmax2 fp16
__device__ __half g_preH[32u * 1024u * 512u];  // fp16(pre)
__device__ __half g_qH [32u * 1024u * 512u];   // fp16(q)
__device__ __half g_vH [32u * 512u * 512u];    // fp16(v)
__device__ __half g_enH[32u * 1024u * 512u];   // fp16(energy)

// ======================= small PTX helpers =================================
__device__ __forceinline__ uint32_t smem_u32(const void* p) {
    uint32_t a;
    asm("{ .reg .u64 t; cvta.to.shared.u64 t, %1; cvt.u32.u64 %0, t; }"
        : "=r"(a) : "l"(p));
    return a;
}
__device__ __forceinline__ void cp_async16(uint32_t dst, const void* src) {
    asm volatile("cp.async.cg.shared.global [%0], [%1], 16;"
                 :: "r"(dst), "l"(src) : "memory");
}
#define CP_COMMIT() asm volatile("cp.async.commit_group;" ::: "memory")
#define CP_WAIT(n)  asm volatile("cp.async.wait_group %0;" :: "n"(n) : "memory")

__device__ __forceinline__ void mma_f16(float* c, const uint32_t* a,
                                        const uint32_t* b) {
    asm volatile(
        "mma.sync.aligned.m16n8k16.row.col.f32.f16.f16.f32 "
        "{%0,%1,%2,%3}, {%4,%5,%6,%7}, {%8,%9}, {%0,%1,%2,%3};"
        : "+f"(c[0]), "+f"(c[1]), "+f"(c[2]), "+f"(c[3])
        : "r"(a[0]), "r"(a[1]), "r"(a[2]), "r"(a[3]), "r"(b[0]), "r"(b[1]));
}
__device__ __forceinline__ void ldsm4(uint32_t* d, uint32_t addr) {
    asm volatile(
        "ldmatrix.sync.aligned.m8n8.x4.shared.b16 {%0,%1,%2,%3}, [%4];"
        : "=r"(d[0]), "=r"(d[1]), "=r"(d[2]), "=r"(d[3]) : "r"(addr));
}
__device__ __forceinline__ void ldsm4t(uint32_t* d, uint32_t addr) {
    asm volatile(
        "ldmatrix.sync.aligned.m8n8.x4.trans.shared.b16 {%0,%1,%2,%3}, [%4];"
        : "=r"(d[0]), "=r"(d[1]), "=r"(d[2]), "=r"(d[3]) : "r"(addr));
}

// ======================= geometry ==========================================
constexpr int BM = 128, BN = 128, BK = 64;
constexpr int ROWA   = 144;                      // A row: 128B data + 16B pad
constexpr int ROWB_T = 144;                      // B NT row: 128B + 16B pad
constexpr int ROWB_N = 272;                      // B NN row: 256B + 16B pad
constexpr int A_BYTES = BM * ROWA;               // 18432
constexpr int STAGES = 3;
constexpr int SMEM_NT = STAGES * (A_BYTES + BN * ROWB_T);  // 110592
constexpr int SMEM_NN = STAGES * (A_BYTES + BK * ROWB_N);  // 107520

// ======================= merged NT score GEMM ==============================
// Computes, in one launch (same M=1024, K=512, alpha=scale):
//   part 0 (blockIdx.x <  SPLIT): S1h = fp16(alpha * preH . qH^T)  N0=1024
//   part 1 (blockIdx.x >= SPLIT): S2h = fp16(alpha * qH  . vH^T)   N1=512
__global__ __launch_bounds__(256, 2)
void mma_nt_dual_kernel(const __half* __restrict__ A0, const __half* __restrict__ B0,
                        __half* __restrict__ Ch0, int N0,
                        const __half* __restrict__ A1, const __half* __restrict__ B1,
                        __half* __restrict__ Ch1, int N1,
                        int M, int K, float alpha, int split)
{
    constexpr int STAGE_BYTES = A_BYTES + BN * ROWB_T;

    extern __shared__ __align__(16) char dyn[];

    const int tid = threadIdx.x;
    const int wid = tid >> 5;
    const int lane = tid & 31;
    const int wm = wid & 1;
    const int wn = wid >> 1;
    const int g = lane >> 2;
    const int qq = lane & 3;

    const bool second = (int)blockIdx.x >= split;
    const int bx = second ? (int)blockIdx.x - split : (int)blockIdx.x;
    const __half* A = second ? A1 : A0;
    const __half* Bm = second ? B1 : B0;
    __half* Ch = second ? Ch1 : Ch0;
    const int N = second ? N1 : N0;

    const int rowA0 = blockIdx.y * BM;
    const int colB0 = bx * BN;

    A  += (size_t)blockIdx.z * M * K + (size_t)rowA0 * K;
    Bm += (size_t)blockIdx.z * N * K + (size_t)colB0 * K;
    Ch += (size_t)blockIdx.z * M * N;

    const uint32_t sbase = smem_u32(dyn);

    float acc[4][4][4];
#pragma unroll
    for (int f = 0; f < 4; f++)
#pragma unroll
        for (int n = 0; n < 4; n++)
#pragma unroll
            for (int i = 0; i < 4; i++) acc[f][n][i] = 0.0f;

    const int KT = K / BK;

    auto load_tile = [&](int kt, int s) {
        const __half* gA = A + (size_t)kt * BK;
        const __half* gB = Bm + (size_t)kt * BK;
        const uint32_t dA = sbase + (uint32_t)(s * STAGE_BYTES);
        const uint32_t dB = dA + (uint32_t)A_BYTES;
#pragma unroll
        for (int i = 0; i < 4; i++) {
            const int ch = tid + i * 256;
            const int r = ch >> 3, c = ch & 7;
            cp_async16(dA + (uint32_t)(r * ROWA + c * 16),
                       gA + (size_t)r * K + c * 8);
        }
#pragma unroll
        for (int i = 0; i < 4; i++) {
            const int ch = tid + i * 256;
            const int r = ch >> 3, c = ch & 7;
            cp_async16(dB + (uint32_t)(r * ROWB_T + c * 16),
                       gB + (size_t)r * K + c * 8);
        }
    };

#pragma unroll
    for (int p = 0; p < STAGES - 1; p++) {
        load_tile(p, p);
        CP_COMMIT();
    }

    const int aRow = (lane & 15);
    const int aKof = (lane >> 4) * 16;
    const int bRowT = (lane & 7) + ((lane >> 4) << 3);
    const int bKofT = ((lane >> 3) & 1) * 16;

    for (int kt = 0; kt < KT; kt++) {
        CP_WAIT(STAGES - 2);
        __syncthreads();                     // also closes reads of tile kt-1

        const int ktn = kt + STAGES - 1;
        if (ktn < KT) load_tile(ktn, ktn % STAGES);
        CP_COMMIT();                         // unconditional: drains tail

        const uint32_t uA = sbase + (uint32_t)((kt % STAGES) * STAGE_BYTES);
        const uint32_t uB = uA + (uint32_t)A_BYTES;

#pragma unroll
        for (int ks = 0; ks < 4; ks++) {
            uint32_t a[4][4], bl[2][4];
#pragma unroll
            for (int f = 0; f < 4; f++) {
                const int row = wm * 64 + f * 16 + aRow;
                ldsm4(a[f], uA + (uint32_t)(row * ROWA + ks * 32 + aKof));
            }
#pragma unroll
            for (int p = 0; p < 2; p++) {
                const int row = wn * 32 + p * 16 + bRowT;
                ldsm4(bl[p], uB + (uint32_t)(row * ROWB_T + ks * 32 + bKofT));
            }
#pragma unroll
            for (int f = 0; f < 4; f++)
#pragma unroll
                for (int n = 0; n < 4; n++)
                    mma_f16(acc[f][n], a[f], &bl[n >> 1][(n & 1) * 2]);
        }
    }

    // epilogue: fp16 store only
#pragma unroll
    for (int f = 0; f < 4; f++) {
        const int row = rowA0 + wm * 64 + f * 16 + g;
#pragma unroll
        for (int n = 0; n < 4; n++) {
            const int col = colB0 + wn * 32 + n * 8 + 2 * qq;
            float2 v0, v1;
            v0.x = acc[f][n][0] * alpha;
            v0.y = acc[f][n][1] * alpha;
            v1.x = acc[f][n][2] * alpha;
            v1.y = acc[f][n][3] * alpha;
            *reinterpret_cast<__half2*>(Ch + (size_t)row * N + col) =
                __float22half2_rn(v0);
            *reinterpret_cast<__half2*>(Ch + (size_t)(row + 8) * N + col) =
                __float22half2_rn(v1);
        }
    }
}

// ======================= NN GEMM (attn . V) ================================
// C = A[M,K] * B[K,N] (B N-major, ldsm.trans). Same core as R15.
__global__ __launch_bounds__(256, 2)
void mma_nn_kernel(const __half* __restrict__ A, const __half* __restrict__ Bm,
                   float* __restrict__ C, __half* __restrict__ Ch,
                   int M, int N, int K)
{
    constexpr int STAGE_BYTES = A_BYTES + BK * ROWB_N;

    extern __shared__ __align__(16) char dyn[];

    const int tid = threadIdx.x;
    const int wid = tid >> 5;
    const int lane = tid & 31;
    const int wm = wid & 1;
    const int wn = wid >> 1;
    const int g = lane >> 2;
    const int qq = lane & 3;

    const int rowA0 = blockIdx.y * BM;
    const int colB0 = blockIdx.x * BN;

    A += (size_t)blockIdx.z * M * K + (size_t)rowA0 * K;
    Bm += (size_t)blockIdx.z * K * N + colB0;

    const uint32_t sbase = smem_u32(dyn);

    float acc[4][4][4];
#pragma unroll
    for (int f = 0; f < 4; f++)
#pragma unroll
        for (int n = 0; n < 4; n++)
#pragma unroll
            for (int i = 0; i < 4; i++) acc[f][n][i] = 0.0f;

    const int KT = K / BK;

    auto load_tile = [&](int kt, int s) {
        const __half* gA = A + (size_t)kt * BK;
        const __half* gB = Bm + (size_t)(kt * BK) * N;
        const uint32_t dA = sbase + (uint32_t)(s * STAGE_BYTES);
        const uint32_t dB = dA + (uint32_t)A_BYTES;
#pragma unroll
        for (int i = 0; i < 4; i++) {
            const int ch = tid + i * 256;
            const int r = ch >> 3, c = ch & 7;
            cp_async16(dA + (uint32_t)(r * ROWA + c * 16),
                       gA + (size_t)r * K + c * 8);
        }
#pragma unroll
        for (int i = 0; i < 4; i++) {
            const int ch = tid + i * 256;
            const int r = ch >> 4, c = ch & 15;
            cp_async16(dB + (uint32_t)(r * ROWB_N + c * 16),
                       gB + (size_t)r * N + c * 8);
        }
    };

#pragma unroll
    for (int p = 0; p < STAGES - 1; p++) {
        load_tile(p, p);
        CP_COMMIT();
    }

    const int aRow = (lane & 15);
    const int aKof = (lane >> 4) * 16;
    const int q8 = lane >> 3;
    const int bKrowN = ((q8 & 1) << 3) + (lane & 7);
    const int bNofN = (q8 >> 1) << 4;

    for (int kt = 0; kt < KT; kt++) {
        CP_WAIT(STAGES - 2);
        __syncthreads();

        const int ktn = kt + STAGES - 1;
        if (ktn < KT) load_tile(ktn, ktn % STAGES);
        CP_COMMIT();

        const uint32_t uA = sbase + (uint32_t)((kt % STAGES) * STAGE_BYTES);
        const uint32_t uB = uA + (uint32_t)A_BYTES;

#pragma unroll
        for (int ks = 0; ks < 4; ks++) {
            uint32_t a[4][4], bl[2][4];
#pragma unroll
            for (int f = 0; f < 4; f++) {
                const int row = wm * 64 + f * 16 + aRow;
                ldsm4(a[f], uA + (uint32_t)(row * ROWA + ks * 32 + aKof));
            }
#pragma unroll
            for (int p = 0; p < 2; p++) {
                const int krow = ks * 16 + bKrowN;
                const int nby = (wn * 32 + p * 16) * 2 + bNofN;
                ldsm4t(bl[p], uB + (uint32_t)(krow * ROWB_N + nby));
            }
#pragma unroll
            for (int f = 0; f < 4; f++)
#pragma unroll
                for (int n = 0; n < 4; n++)
                    mma_f16(acc[f][n], a[f], &bl[n >> 1][(n & 1) * 2]);
        }
    }

    float* Cb = C + (size_t)blockIdx.z * M * N;
    __half* Chb = Ch ? Ch + (size_t)blockIdx.z * M * N : (__half*)0;
#pragma unroll
    for (int f = 0; f < 4; f++) {
        const int row = rowA0 + wm * 64 + f * 16 + g;
#pragma unroll
        for (int n = 0; n < 4; n++) {
            const int col = colB0 + wn * 32 + n * 8 + 2 * qq;
            float2 v0, v1;
            v0.x = acc[f][n][0];
            v0.y = acc[f][n][1];
            v1.x = acc[f][n][2];
            v1.y = acc[f][n][3];
            *reinterpret_cast<float2*>(Cb + (size_t)row * N + col) = v0;
            *reinterpret_cast<float2*>(Cb + (size_t)(row + 8) * N + col) = v1;
            if (Chb) {
                *reinterpret_cast<__half2*>(Chb + (size_t)row * N + col) =
                    __float22half2_rn(v0);
                *reinterpret_cast<__half2*>(Chb + (size_t)(row + 8) * N + col) =
                    __float22half2_rn(v1);
            }
        }
    }
}

// ======================= merged fp32 -> fp16 convert =======================
// One launch converts pre (nPQ), q (nPQ), v (nV); 8 elements per thread.
__global__ __launch_bounds__(256)
void h_convert_all_kernel(const float* __restrict__ pre, __half* __restrict__ preH,
                          const float* __restrict__ q, __half* __restrict__ qH,
                          const float* __restrict__ v, __half* __restrict__ vH,
                          int nPQ8, int nV8)  // counts in units of 8 elements
{
    int idx = blockIdx.x * 256 + threadIdx.x;
    const float* in;
    __half* out;
    if (idx < nPQ8) {
        in = q; out = qH;                    // q first: needed by both chains
    } else if (idx < 2 * nPQ8) {
        idx -= nPQ8; in = pre; out = preH;
    } else {
        idx -= 2 * nPQ8; in = v; out = vH;
        if (idx >= nV8) return;
    }
    const size_t i = (size_t)idx * 8;
    float4 v0 = *reinterpret_cast<const float4*>(in + i);
    float4 v1 = *reinterpret_cast<const float4*>(in + i + 4);
    __half2 h[4];
    h[0] = __float22half2_rn(make_float2(v0.x, v0.y));
    h[1] = __float22half2_rn(make_float2(v0.z, v0.w));
    h[2] = __float22half2_rn(make_float2(v1.x, v1.y));
    h[3] = __float22half2_rn(make_float2(v1.z, v1.w));
    *reinterpret_cast<uint4*>(out + i) = *reinterpret_cast<uint4*>(h);
}

// ======================= row softmax (fp16 in place, fp32 math) ============
template <int ELEMS>   // halves per thread; W = 256*ELEMS
__global__ __launch_bounds__(256)
void softmax_rows_h_kernel(__half* __restrict__ Sh, int W)
{
    __half* ph = Sh + (size_t)blockIdx.x * W + (size_t)threadIdx.x * ELEMS;
    const int tid = threadIdx.x;

    float vals[ELEMS];
    if (ELEMS == 4) {
        uint2 raw = *reinterpret_cast<const uint2*>(ph);
        __half2 h0 = *reinterpret_cast<__half2*>(&raw.x);
        __half2 h1 = *reinterpret_cast<__half2*>(&raw.y);
        float2 f0 = __half22float2(h0);
        float2 f1 = __half22float2(h1);
        vals[0] = f0.x; vals[1] = f0.y; vals[2] = f1.x; vals[3] = f1.y;
    } else {
        uint32_t raw = *reinterpret_cast<const uint32_t*>(ph);
        __half2 h0 = *reinterpret_cast<__half2*>(&raw);
        float2 f0 = __half22float2(h0);
        vals[0] = f0.x; vals[1] = f0.y;
    }

    float m = vals[0];
#pragma unroll
    for (int i = 1; i < ELEMS; i++) m = fmaxf(m, vals[i]);

    __shared__ float red[8];
    __shared__ float bc;

#pragma unroll
    for (int o = 16; o > 0; o >>= 1)
        m = fmaxf(m, __shfl_xor_sync(0xffffffffu, m, o));
    if ((tid & 31) == 0) red[tid >> 5] = m;
    __syncthreads();
    if (tid == 0) {
        float t = red[0];
#pragma unroll
        for (int i = 1; i < 8; i++) t = fmaxf(t, red[i]);
        bc = t;
    }
    __syncthreads();
    m = bc;

    float s = 0.0f;
#pragma unroll
    for (int i = 0; i < ELEMS; i++) {
        vals[i] = expf(vals[i] - m);
        s += vals[i];
    }
    __syncthreads();

#pragma unroll
    for (int o = 16; o > 0; o >>= 1)
        s += __shfl_xor_sync(0xffffffffu, s, o);
    if ((tid & 31) == 0) red[tid >> 5] = s;
    __syncthreads();
    if (tid == 0) {
        float t = red[0];
#pragma unroll
        for (int i = 1; i < 8; i++) t += red[i];
        bc = 1.0f / t;
    }
    __syncthreads();
    const float inv = bc;

    if (ELEMS == 4) {
        __half2 h0 = __float22half2_rn(make_float2(vals[0] * inv, vals[1] * inv));
        __half2 h1 = __float22half2_rn(make_float2(vals[2] * inv, vals[3] * inv));
        uint2 o;
        o.x = *reinterpret_cast<uint32_t*>(&h0);
        o.y = *reinterpret_cast<uint32_t*>(&h1);
        *reinterpret_cast<uint2*>(ph) = o;
    } else {
        __half2 h0 = __float22half2_rn(make_float2(vals[0] * inv, vals[1] * inv));
        *reinterpret_cast<uint32_t*>(ph) = *reinterpret_cast<uint32_t*>(&h0);
    }
}

}  // namespace

// ===========================================================================
extern "C" void kernel_launch(void* const* d_in, const int* in_sizes, int n_in,
                              void* d_out, int out_size)
{
    const float* pre = (const float*)d_in[0];  // [32,1024,512]
    const float* q   = (const float*)d_in[1];  // [32,1024,512]
    const float* v   = (const float*)d_in[2];  // [32, 512,512]
    float* out = (float*)d_out;

    const int B = 32, Lp = 1024, Lq = 1024, Lv = 512, D = 512;
    const float scale = 0.04419417382415922f;  // 1/sqrt(512)

    float* wc     = out;                           // [B,Lq,D]
    float* energy = out + (size_t)B * Lq * D;      // [B,Lq,D]
    float* prec   = out + 2 * (size_t)B * Lq * D;  // [B,Lp,D]

    __half *S1h, *S2h, *preH, *qH, *vH, *enH;
    cudaGetSymbolAddress((void**)&S1h, g_S1h);
    cudaGetSymbolAddress((void**)&S2h, g_S2h);
    cudaGetSymbolAddress((void**)&preH, g_preH);
    cudaGetSymbolAddress((void**)&qH, g_qH);
    cudaGetSymbolAddress((void**)&vH, g_vH);
    cudaGetSymbolAddress((void**)&enH, g_enH);

    // one-time setup (first call is the uncaptured correctness run)
    static cudaStream_t sB = 0;
    static cudaEvent_t eFork = 0, eJoin = 0;
    if (!sB) {
        cudaStreamCreateWithFlags(&sB, cudaStreamNonBlocking);
        cudaEventCreateWithFlags(&eFork, cudaEventDisableTiming);
        cudaEventCreateWithFlags(&eJoin, cudaEventDisableTiming);
        cudaFuncSetAttribute(mma_nt_dual_kernel,
                             cudaFuncAttributeMaxDynamicSharedMemorySize,
                             SMEM_NT);
        cudaFuncSetAttribute(mma_nn_kernel,
                             cudaFuncAttributeMaxDynamicSharedMemorySize,
                             SMEM_NN);
    }

    const int nPQ = B * Lp * D;   // 16.8M
    const int nV  = B * Lv * D;   // 8.4M
    const int nPQ8 = nPQ / 8, nV8 = nV / 8;
    const dim3 blk(256);
    cudaStream_t sA = 0;          // legacy default stream (captured origin)

    // merged converts (q, pre, v) — one launch
    const int convBlocks = (2 * nPQ8 + nV8 + 255) / 256;
    h_convert_all_kernel<<<convBlocks, 256, 0, sA>>>(
        pre, preH, q, qH, v, vH, nPQ8, nV8);

    // merged score GEMMs: S1h (8 col-tiles) + S2h (4 col-tiles), one launch
    const int SPLIT = Lq / BN;    // 8
    mma_nt_dual_kernel<<<dim3(SPLIT + Lv / BN, Lp / BM, B), blk, SMEM_NT, sA>>>(
        preH, qH, S1h, Lq,
        qH, vH, S2h, Lv,
        Lp, D, scale, SPLIT);

    // fork chain B after scores are ready
    cudaEventRecord(eFork, sA);
    cudaStreamWaitEvent(sB, eFork, 0);

    // ---- chain B (stream sB): softmax2 -> energy -> wc ----
    softmax_rows_h_kernel<2><<<B * Lq, 256, 0, sB>>>(S2h, Lv);
    mma_nn_kernel<<<dim3(D / BN, Lq / BM, B), blk, SMEM_NN, sB>>>(
        S2h, vH, energy, enH, Lq, D, Lv);
    mma_nn_kernel<<<dim3(D / BN, Lq / BM, B), blk, SMEM_NN, sB>>>(
        enH, vH, wc, nullptr, Lq, D, Lv);

    // ---- chain A (stream sA): softmax1 -> prec ----
    softmax_rows_h_kernel<4><<<B * Lp, 256, 0, sA>>>(S1h, Lq);
    mma_nn_kernel<<<dim3(D / BN, Lp / BM, B), blk, SMEM_NN, sA>>>(
        S1h, qH, prec, nullptr, Lp, D, Lq);

    // join
    cudaEventRecord(eJoin, sB);
    cudaStreamWaitEvent(sA, eJoin, 0);
}